// round 8
// baseline (speedup 1.0000x reference)
#include <cuda_runtime.h>
#include <cuda_fp16.h>
#include <cstdint>

#define DM   512
#define LSEQ 2048
#define BSZ  8
#define MTOT (BSZ * LSEQ)      /* 16384 rows */
#define NCH  64
#define CHUNK (LSEQ / NCH)     /* 32 */
#define NSP  8                 /* S partial chunks (t < 256) */

// Scratch (allocation-free: __device__ globals)
__device__ float  g_h[(size_t)MTOT * DM];           // 33.5 MB (raw GEMM output)
__device__ __half g_xh[(size_t)MTOT * DM];          // 16.7 MB (X in fp16)
__device__ __half g_wh[(size_t)DM * DM];            // 0.5 MB (W in fp16)
__device__ float  g_mu[MTOT];
__device__ float  g_rs[MTOT];
__device__ float  g_csum[BSZ * NCH * DM];
__device__ float  g_Sre[BSZ * NSP * DM];
__device__ float  g_Sim[BSZ * NSP * DM];

// ===========================================================================
// PTX helpers (arch-portable: sm_80+ path, no 'a' features)
// ===========================================================================
static __device__ __forceinline__ uint32_t smem_u32(const void* p) {
    uint32_t a;
    asm("{ .reg .u64 t; cvta.to.shared.u64 t, %1; cvt.u32.u64 %0, t; }"
        : "=r"(a) : "l"(p));
    return a;
}
static __device__ __forceinline__ void ldsm_x4(uint32_t* r, uint32_t addr) {
    asm volatile("ldmatrix.sync.aligned.m8n8.x4.shared.b16 {%0,%1,%2,%3}, [%4];"
                 : "=r"(r[0]), "=r"(r[1]), "=r"(r[2]), "=r"(r[3]) : "r"(addr));
}
static __device__ __forceinline__ void mma_f16(float* c, const uint32_t* a,
                                               const uint32_t* b) {
    asm volatile(
        "mma.sync.aligned.m16n8k16.row.col.f32.f16.f16.f32 "
        "{%0,%1,%2,%3},{%4,%5,%6,%7},{%8,%9},{%0,%1,%2,%3};"
        : "+f"(c[0]), "+f"(c[1]), "+f"(c[2]), "+f"(c[3])
        : "r"(a[0]), "r"(a[1]), "r"(a[2]), "r"(a[3]), "r"(b[0]), "r"(b[1]));
}
#define CP16(dst, src) \
    asm volatile("cp.async.ca.shared.global [%0], [%1], 16;" \
                 :: "r"(dst), "l"(src) : "memory")
#define CP_COMMIT() asm volatile("cp.async.commit_group;" ::: "memory")
#define CP_WAIT1()  asm volatile("cp.async.wait_group 1;" ::: "memory")

static __device__ __forceinline__ uint32_t pack_h2(__half a, __half b) {
    return ((uint32_t)__half_as_ushort(b) << 16) | __half_as_ushort(a);
}
static __device__ __forceinline__ uint2 cvt4h(float4 v) {
    uint2 r;
    r.x = pack_h2(__float2half_rn(v.x), __float2half_rn(v.y));
    r.y = pack_h2(__float2half_rn(v.z), __float2half_rn(v.w));
    return r;
}

// ===========================================================================
// Kernel 0: fp32 -> fp16 pre-convert of X and W (pure streaming)
// ===========================================================================
#define N4X ((MTOT * DM) / 4)
#define N4W ((DM * DM) / 4)
__global__ __launch_bounds__(256)
void cvt_kernel(const float* __restrict__ X, const float* __restrict__ W)
{
    const int idx = blockIdx.x * 256 + threadIdx.x;
    const int stride = gridDim.x * 256;
    for (int i = idx; i < N4X + N4W; i += stride) {
        if (i < N4X) {
            const float4 v = *(const float4*)(X + (size_t)i * 4);
            *(uint2*)(g_xh + (size_t)i * 4) = cvt4h(v);
        } else {
            const int j = i - N4X;
            const float4 v = *(const float4*)(W + (size_t)j * 4);
            *(uint2*)(g_wh + (size_t)j * 4) = cvt4h(v);
        }
    }
}

// ===========================================================================
// Kernel 1: fp16 mma.sync GEMM with cp.async 3-stage pipeline.
// H = X W^T + bias.  CTA tile 256x256 (grid = 64x2 = 128 CTAs = one wave),
// 512 threads / 16 warps, warp tile 64x64, K-chunks of 32.
// SMEM layout per stage: A 256 rows x 80B, then B 256 rows x 80B.
// ===========================================================================
#define KC       32
#define NKC      (DM / KC)                 /* 16 chunks */
#define ROW_B    80                        /* bytes per smem row (32 halfs+pad) */
#define HTILE_B  (256 * ROW_B)             /* 20480 B per operand tile */
#define STAGE_B  (2 * HTILE_B)             /* 40960 B per stage */
#define NSTG     3
#define SMEM_G   (NSTG * STAGE_B)          /* 122880 B */

__global__ __launch_bounds__(512, 1)
void gemm_mma_kernel(const float* __restrict__ bias)
{
    extern __shared__ char smem[];
    const uint32_t sb = smem_u32(smem);
    const int tid  = threadIdx.x;
    const int wid  = tid >> 5;
    const int lane = tid & 31;
    const int bm   = blockIdx.y * 256;
    const int bn   = blockIdx.x * 256;
    const int wm   = (wid & 3) * 64;       // 4 m-strips of 64
    const int wn   = (wid >> 2) * 64;      // 4 n-strips of 64

    // each thread issues 2 A-chunks + 2 B-chunks of 16B per stage
    const int p0 = tid * 2;                // 0..1022
    const int r0 = p0 >> 2, c0 = (p0 & 3); // row 0..255, chunk 0..3
    const int p1 = p0 + 1;
    const int r1 = p1 >> 2, c1 = (p1 & 3);

    const __half* Xb = g_xh + (size_t)bm * DM;
    const __half* Wb = g_wh + (size_t)bn * DM;

    auto issue_stage = [&](int kc, int stg) {
        const uint32_t sA = sb + stg * STAGE_B;
        const uint32_t sB = sA + HTILE_B;
        const int ko = kc * KC;
        CP16(sA + r0 * ROW_B + c0 * 16, Xb + (size_t)r0 * DM + ko + c0 * 8);
        CP16(sA + r1 * ROW_B + c1 * 16, Xb + (size_t)r1 * DM + ko + c1 * 8);
        CP16(sB + r0 * ROW_B + c0 * 16, Wb + (size_t)r0 * DM + ko + c0 * 8);
        CP16(sB + r1 * ROW_B + c1 * 16, Wb + (size_t)r1 * DM + ko + c1 * 8);
    };

    float acc[4][8][4];
#pragma unroll
    for (int mt = 0; mt < 4; ++mt)
#pragma unroll
        for (int nt = 0; nt < 8; ++nt)
#pragma unroll
            for (int q = 0; q < 4; ++q) acc[mt][nt][q] = 0.0f;

    // prologue: stages 0,1 in flight
    issue_stage(0, 0); CP_COMMIT();
    issue_stage(1, 1); CP_COMMIT();

    const int a_lr  = lane & 15;
    const int a_lk  = (lane >> 4) * 8;
    const int b_nr  = ((lane >> 4) & 1) * 8 + (lane & 7);
    const int b_lk  = ((lane >> 3) & 1) * 8;

    for (int kc = 0; kc < NKC; ++kc) {
        CP_WAIT1();                 // stage kc resident
        __syncthreads();            // all warps past stage kc-1 reads
        if (kc + 2 < NKC) issue_stage(kc + 2, (kc + 2) % NSTG);
        CP_COMMIT();

        const uint32_t sA = sb + (kc % NSTG) * STAGE_B;
        const uint32_t sB = sA + HTILE_B;

#pragma unroll
        for (int ks = 0; ks < 2; ++ks) {
            uint32_t ah[4][4], bf[8][2];
#pragma unroll
            for (int mt = 0; mt < 4; ++mt) {
                const uint32_t aaddr = sA +
                    (uint32_t)((wm + mt * 16 + a_lr) * ROW_B + (ks * 16 + a_lk) * 2);
                ldsm_x4(ah[mt], aaddr);
            }
#pragma unroll
            for (int np = 0; np < 4; ++np) {
                const uint32_t baddr = sB +
                    (uint32_t)((wn + np * 16 + b_nr) * ROW_B + (ks * 16 + b_lk) * 2);
                uint32_t t[4];
                ldsm_x4(t, baddr);
                bf[np * 2][0] = t[0]; bf[np * 2][1] = t[1];
                bf[np * 2 + 1][0] = t[2]; bf[np * 2 + 1][1] = t[3];
            }
#pragma unroll
            for (int mt = 0; mt < 4; ++mt)
#pragma unroll
                for (int nt = 0; nt < 8; ++nt)
                    mma_f16(acc[mt][nt], ah[mt], bf[nt]);
        }
    }

    // epilogue: +bias, direct fp32 stores
    const int gq = lane >> 2;
    const int r2 = (lane & 3) * 2;
#pragma unroll
    for (int mt = 0; mt < 4; ++mt) {
        const int row0 = bm + wm + mt * 16 + gq;
#pragma unroll
        for (int nt = 0; nt < 8; ++nt) {
            const int col = bn + wn + nt * 8 + r2;
            const float2 bv = *(const float2*)(bias + col);
            float2 v0, v1;
            v0.x = acc[mt][nt][0] + bv.x;
            v0.y = acc[mt][nt][1] + bv.y;
            v1.x = acc[mt][nt][2] + bv.x;
            v1.y = acc[mt][nt][3] + bv.y;
            *(float2*)(g_h + (size_t)row0 * DM + col)       = v0;
            *(float2*)(g_h + (size_t)(row0 + 8) * DM + col) = v1;
        }
    }
}

// ===========================================================================
// Kernel 2 (fused): per-row LN stats + chunk sums of normalized h + windowed
// complex S partials (chunks c < NSP). grid = (NCH=64, BSZ), 512 threads.
// ===========================================================================
__global__ __launch_bounds__(512)
void stat_pass1_kernel(const float* __restrict__ Are, const float* __restrict__ Aim,
                       const float* __restrict__ gamma, const float* __restrict__ beta)
{
    __shared__ float s_mu[CHUNK], s_rs[CHUNK];
    const int tid  = threadIdx.x;
    const int warp = tid >> 5;
    const int lane = tid & 31;
    const int c = blockIdx.x;
    const int b = blockIdx.y;
    const size_t row0 = (size_t)b * LSEQ + (size_t)c * CHUNK;

#pragma unroll
    for (int j = 0; j < 2; ++j) {
        const int i = warp * 2 + j;
        const float* p = g_h + (row0 + i) * DM;
        float s = 0.0f, s2 = 0.0f;
#pragma unroll
        for (int q = 0; q < 4; ++q) {
            const float4 v = *(const float4*)(p + lane * 4 + q * 128);
            s  += v.x + v.y + v.z + v.w;
            s2 += v.x * v.x + v.y * v.y + v.z * v.z + v.w * v.w;
        }
#pragma unroll
        for (int o = 16; o > 0; o >>= 1) {
            s  += __shfl_xor_sync(0xFFFFFFFFu, s,  o);
            s2 += __shfl_xor_sync(0xFFFFFFFFu, s2, o);
        }
        if (lane == 0) {
            const float mu   = s * (1.0f / DM);
            const float var  = s2 * (1.0f / DM) - mu * mu;
            const float rstd = rsqrtf(var + 1e-5f);
            s_mu[i] = mu;  s_rs[i] = rstd;
            g_mu[row0 + i] = mu;  g_rs[row0 + i] = rstd;
        }
    }
    __syncthreads();

    const int d = tid;
    const float gd = gamma[d], bd = beta[d];
    const float* p = g_h + row0 * DM + d;

    if (c < NSP) {
        const float are = Are[d], aim = Aim[d];
        float s = 0.0f;
        float pre = 1.0f, pim = 0.0f, Sre = 0.0f, Sim = 0.0f;
        for (int i = 0; i < CHUNK; ++i) {
            const float hn = (p[(size_t)i * DM] - s_mu[i]) * s_rs[i] * gd + bd;
            s += hn;
            Sre = fmaf(pre, hn, Sre);
            Sim = fmaf(pim, hn, Sim);
            const float nre = pre * are - pim * aim;
            const float nim = pre * aim + pim * are;
            pre = nre; pim = nim;
        }
        g_csum[(b * NCH + c) * DM + d] = s;
        float wre = 1.0f, wim = 0.0f;
        if (c > 0) {
            float tre = are, tim = aim;
#pragma unroll
            for (int k = 0; k < 5; ++k) {
                const float nr = tre * tre - tim * tim;
                const float ni = 2.0f * tre * tim;
                tre = nr; tim = ni;
            }
            for (int j = 0; j < c; ++j) {
                const float nr = wre * tre - wim * tim;
                const float ni = wre * tim + wim * tre;
                wre = nr; wim = ni;
            }
        }
        g_Sre[(b * NSP + c) * DM + d] = Sre * wre - Sim * wim;
        g_Sim[(b * NSP + c) * DM + d] = Sre * wim + Sim * wre;
    } else {
        float s0 = 0.f, s1 = 0.f;
#pragma unroll 2
        for (int i = 0; i < CHUNK; i += 2) {
            s0 += (p[(size_t)(i + 0) * DM] - s_mu[i + 0]) * s_rs[i + 0];
            s1 += (p[(size_t)(i + 1) * DM] - s_mu[i + 1]) * s_rs[i + 1];
        }
        g_csum[(b * NCH + c) * DM + d] = fmaf(gd, s0 + s1, (float)CHUNK * bd);
    }
}

// ===========================================================================
// Kernel 3: y[l] = hn[l] + ReDc*prefix(hn)[l]; last chunk adds
// Re(BC * A^(L-1-l) * S).  grid = (NCH=64, BSZ), 512 threads.
// ===========================================================================
__global__ __launch_bounds__(512)
void pass2_kernel(float* __restrict__ Y,
                  const float* __restrict__ Are, const float* __restrict__ Aim,
                  const float* __restrict__ Bre, const float* __restrict__ Bim,
                  const float* __restrict__ Cre, const float* __restrict__ Cim,
                  const float* __restrict__ Dre,
                  const float* __restrict__ gamma, const float* __restrict__ beta)
{
    __shared__ float s_mu[CHUNK], s_rs[CHUNK];
    const int d = threadIdx.x;
    const int c = blockIdx.x;
    const int b = blockIdx.y;
    const size_t row0 = (size_t)b * LSEQ + (size_t)c * CHUNK;

    if (d < CHUNK) {
        s_mu[d] = g_mu[row0 + d];
        s_rs[d] = g_rs[row0 + d];
    }
    __syncthreads();

    const float* cs = g_csum + (size_t)b * NCH * DM + d;
    float off = 0.0f;
    for (int cc = 0; cc < c; ++cc) off += cs[(size_t)cc * DM];

    const size_t base = row0 * DM + d;
    const float gd = gamma[d], bd = beta[d];
    const float dre = Dre[d];
    float run = off;
    for (int i = 0; i < CHUNK; ++i) {
        const float hn = (g_h[base + (size_t)i * DM] - s_mu[i]) * s_rs[i] * gd + bd;
        run += hn;
        Y[base + (size_t)i * DM] = fmaf(dre, run, hn);
    }

    if (c == NCH - 1) {
        const float are = Are[d], aim = Aim[d];
        const float bre = Bre[d], bim = Bim[d];
        const float cre = Cre[d], cim = Cim[d];
        const float bcre = bre * cre - bim * cim;
        const float bcim = bre * cim + bim * cre;
        float Sre = 0.0f, Sim = 0.0f;
#pragma unroll
        for (int j = 0; j < NSP; ++j) {
            Sre += g_Sre[(b * NSP + j) * DM + d];
            Sim += g_Sim[(b * NSP + j) * DM + d];
        }
        float qre = 1.0f, qim = 0.0f;
        for (int i = CHUNK - 1; i >= 0; --i) {
            const size_t idx = base + (size_t)i * DM;
            const float zre = qre * Sre - qim * Sim;
            const float zim = qre * Sim + qim * Sre;
            Y[idx] += bcre * zre - bcim * zim;
            const float nre = qre * are - qim * aim;
            const float nim = qre * aim + qim * are;
            qre = nre; qim = nim;
        }
    }
}

// ---------------------------------------------------------------------------
extern "C" void kernel_launch(void* const* d_in, const int* in_sizes, int n_in,
                              void* d_out, int out_size)
{
    const float* x    = (const float*)d_in[0];
    const float* Are  = (const float*)d_in[1];
    const float* Aim  = (const float*)d_in[2];
    const float* Bre  = (const float*)d_in[3];
    const float* Bim  = (const float*)d_in[4];
    const float* Cre  = (const float*)d_in[5];
    const float* Cim  = (const float*)d_in[6];
    const float* Dre  = (const float*)d_in[7];
    const float* W    = (const float*)d_in[9];
    const float* bias = (const float*)d_in[10];
    const float* gamma= (const float*)d_in[11];
    const float* beta = (const float*)d_in[12];
    float* out = (float*)d_out;

    cudaFuncSetAttribute(gemm_mma_kernel,
                         cudaFuncAttributeMaxDynamicSharedMemorySize, SMEM_G);
    cvt_kernel<<<1184, 256>>>(x, W);
    gemm_mma_kernel<<<dim3(2, 64), 512, SMEM_G>>>(bias);
    stat_pass1_kernel<<<dim3(NCH, BSZ), DM>>>(Are, Aim, gamma, beta);
    pass2_kernel<<<dim3(NCH, BSZ), DM>>>(out, Are, Aim, Bre, Bim, Cre, Cim, Dre,
                                         gamma, beta);
}

// round 9
// speedup vs baseline: 1.5977x; 1.5977x over previous
#include <cuda_runtime.h>
#include <cuda_fp16.h>
#include <cstdint>

#define DM   512
#define LSEQ 2048
#define BSZ  8
#define MTOT (BSZ * LSEQ)      /* 16384 rows */
#define NCH  64
#define CHUNK (LSEQ / NCH)     /* 32 */
#define NSP  8                 /* S partial chunks (t < 256) */

// Scratch (allocation-free: __device__ globals)
__device__ float  g_h[(size_t)MTOT * DM];           // 33.5 MB (raw GEMM output)
__device__ __half g_xh[(size_t)MTOT * DM];          // 16.7 MB (X in fp16)
__device__ __half g_wh[(size_t)DM * DM];            // 0.5 MB (W in fp16)
__device__ float  g_mu[MTOT];
__device__ float  g_rs[MTOT];
__device__ float  g_csum[BSZ * NCH * DM];
__device__ float  g_Sre[BSZ * NSP * DM];
__device__ float  g_Sim[BSZ * NSP * DM];

// ===========================================================================
// PTX helpers (arch-portable: sm_80+ path, no 'a' features)
// ===========================================================================
static __device__ __forceinline__ uint32_t smem_u32(const void* p) {
    uint32_t a;
    asm("{ .reg .u64 t; cvta.to.shared.u64 t, %1; cvt.u32.u64 %0, t; }"
        : "=r"(a) : "l"(p));
    return a;
}
static __device__ __forceinline__ void ldsm_x4(uint32_t* r, uint32_t addr) {
    asm volatile("ldmatrix.sync.aligned.m8n8.x4.shared.b16 {%0,%1,%2,%3}, [%4];"
                 : "=r"(r[0]), "=r"(r[1]), "=r"(r[2]), "=r"(r[3]) : "r"(addr));
}
static __device__ __forceinline__ void mma_f16(float* c, const uint32_t* a,
                                               const uint32_t* b) {
    asm volatile(
        "mma.sync.aligned.m16n8k16.row.col.f32.f16.f16.f32 "
        "{%0,%1,%2,%3},{%4,%5,%6,%7},{%8,%9},{%0,%1,%2,%3};"
        : "+f"(c[0]), "+f"(c[1]), "+f"(c[2]), "+f"(c[3])
        : "r"(a[0]), "r"(a[1]), "r"(a[2]), "r"(a[3]), "r"(b[0]), "r"(b[1]));
}
#define CP16(dst, src) \
    asm volatile("cp.async.ca.shared.global [%0], [%1], 16;" \
                 :: "r"(dst), "l"(src) : "memory")
#define CP_COMMIT() asm volatile("cp.async.commit_group;" ::: "memory")
#define CP_WAIT2()  asm volatile("cp.async.wait_group 2;" ::: "memory")

static __device__ __forceinline__ uint32_t pack_h2(__half a, __half b) {
    return ((uint32_t)__half_as_ushort(b) << 16) | __half_as_ushort(a);
}
static __device__ __forceinline__ uint2 cvt4h(float4 v) {
    uint2 r;
    r.x = pack_h2(__float2half_rn(v.x), __float2half_rn(v.y));
    r.y = pack_h2(__float2half_rn(v.z), __float2half_rn(v.w));
    return r;
}

// ===========================================================================
// Kernel 0: fp32 -> fp16 pre-convert of X and W (pure streaming)
// ===========================================================================
#define N4X ((MTOT * DM) / 4)
#define N4W ((DM * DM) / 4)
__global__ __launch_bounds__(256)
void cvt_kernel(const float* __restrict__ X, const float* __restrict__ W)
{
    const int idx = blockIdx.x * 256 + threadIdx.x;
    const int stride = gridDim.x * 256;
    for (int i = idx; i < N4X + N4W; i += stride) {
        if (i < N4X) {
            const float4 v = *(const float4*)(X + (size_t)i * 4);
            *(uint2*)(g_xh + (size_t)i * 4) = cvt4h(v);
        } else {
            const int j = i - N4X;
            const float4 v = *(const float4*)(W + (size_t)j * 4);
            *(uint2*)(g_wh + (size_t)j * 4) = cvt4h(v);
        }
    }
}

// ===========================================================================
// Kernel 1: fp16 mma.sync GEMM, cp.async 4-stage pipeline, no hot-loop cvt.
// H = X W^T + bias.  CTA tile 128x128, 256 threads / 8 warps (warp 64x32),
// 2 CTAs/SM.  K-chunks of 32.
// ===========================================================================
#define KC       32
#define NKC      (DM / KC)                 /* 16 chunks */
#define ROW_B    80                        /* bytes/smem row: 64B data + pad */
#define HTILE_B  (128 * ROW_B)             /* 10240 B per operand tile */
#define STAGE_B  (2 * HTILE_B)             /* 20480 B per stage */
#define NSTG     4
#define SMEM_G   (NSTG * STAGE_B)          /* 81920 B per CTA */

__global__ __launch_bounds__(256, 2)
void gemm_mma_kernel(const float* __restrict__ bias)
{
    extern __shared__ char smem[];
    const uint32_t sb = smem_u32(smem);
    const int tid  = threadIdx.x;
    const int wid  = tid >> 5;
    const int lane = tid & 31;
    const int bm   = blockIdx.y * 128;
    const int bn   = blockIdx.x * 128;
    const int wm   = (wid & 1) * 64;       // 2 m-strips of 64
    const int wn   = (wid >> 1) * 32;      // 4 n-strips of 32

    // cp.async mapping: 128 rows x 4 x 16B per operand; 2 A + 2 B per thread
    const int p0 = tid * 2;                // 0..510
    const int r0 = p0 >> 2, c0 = p0 & 3;
    const int p1 = p0 + 1;
    const int r1 = p1 >> 2, c1 = p1 & 3;

    const __half* Xb = g_xh + (size_t)bm * DM;
    const __half* Wb = g_wh + (size_t)bn * DM;

    auto issue_stage = [&](int kc, int stg) {
        const uint32_t sA = sb + stg * STAGE_B;
        const uint32_t sB = sA + HTILE_B;
        const int ko = kc * KC;
        CP16(sA + r0 * ROW_B + c0 * 16, Xb + (size_t)r0 * DM + ko + c0 * 8);
        CP16(sA + r1 * ROW_B + c1 * 16, Xb + (size_t)r1 * DM + ko + c1 * 8);
        CP16(sB + r0 * ROW_B + c0 * 16, Wb + (size_t)r0 * DM + ko + c0 * 8);
        CP16(sB + r1 * ROW_B + c1 * 16, Wb + (size_t)r1 * DM + ko + c1 * 8);
    };

    float acc[4][4][4];
#pragma unroll
    for (int mt = 0; mt < 4; ++mt)
#pragma unroll
        for (int nt = 0; nt < 4; ++nt)
#pragma unroll
            for (int q = 0; q < 4; ++q) acc[mt][nt][q] = 0.0f;

    // prologue: stages 0..2 in flight
    issue_stage(0, 0); CP_COMMIT();
    issue_stage(1, 1); CP_COMMIT();
    issue_stage(2, 2); CP_COMMIT();

    const int a_lr  = lane & 15;
    const int a_lk  = (lane >> 4) * 8;
    const int b_nr  = ((lane >> 4) & 1) * 8 + (lane & 7);
    const int b_lk  = ((lane >> 3) & 1) * 8;

    for (int kc = 0; kc < NKC; ++kc) {
        CP_WAIT2();                 // stage kc resident (<=2 newer pending)
        __syncthreads();            // all warps done reading stage (kc-1)%4
        if (kc + 3 < NKC) issue_stage(kc + 3, (kc + 3) % NSTG);
        CP_COMMIT();

        const uint32_t sA = sb + (kc % NSTG) * STAGE_B;
        const uint32_t sB = sA + HTILE_B;

#pragma unroll
        for (int ks = 0; ks < 2; ++ks) {
            uint32_t ah[4][4], bf[4][2];
#pragma unroll
            for (int mt = 0; mt < 4; ++mt) {
                const uint32_t aaddr = sA +
                    (uint32_t)((wm + mt * 16 + a_lr) * ROW_B + (ks * 16 + a_lk) * 2);
                ldsm_x4(ah[mt], aaddr);
            }
#pragma unroll
            for (int np = 0; np < 2; ++np) {
                const uint32_t baddr = sB +
                    (uint32_t)((wn + np * 16 + b_nr) * ROW_B + (ks * 16 + b_lk) * 2);
                uint32_t t[4];
                ldsm_x4(t, baddr);
                bf[np * 2][0] = t[0]; bf[np * 2][1] = t[1];
                bf[np * 2 + 1][0] = t[2]; bf[np * 2 + 1][1] = t[3];
            }
#pragma unroll
            for (int mt = 0; mt < 4; ++mt)
#pragma unroll
                for (int nt = 0; nt < 4; ++nt)
                    mma_f16(acc[mt][nt], ah[mt], bf[nt]);
        }
    }

    // epilogue: +bias, direct fp32 stores
    const int gq = lane >> 2;
    const int r2 = (lane & 3) * 2;
    float2 bv[4];
#pragma unroll
    for (int nt = 0; nt < 4; ++nt)
        bv[nt] = *(const float2*)(bias + bn + wn + nt * 8 + r2);
#pragma unroll
    for (int mt = 0; mt < 4; ++mt) {
        const int row0 = bm + wm + mt * 16 + gq;
#pragma unroll
        for (int nt = 0; nt < 4; ++nt) {
            const int col = bn + wn + nt * 8 + r2;
            float2 v0, v1;
            v0.x = acc[mt][nt][0] + bv[nt].x;
            v0.y = acc[mt][nt][1] + bv[nt].y;
            v1.x = acc[mt][nt][2] + bv[nt].x;
            v1.y = acc[mt][nt][3] + bv[nt].y;
            *(float2*)(g_h + (size_t)row0 * DM + col)       = v0;
            *(float2*)(g_h + (size_t)(row0 + 8) * DM + col) = v1;
        }
    }
}

// ===========================================================================
// Kernel 2 (fused): per-row LN stats + chunk sums of normalized h + windowed
// complex S partials (chunks c < NSP). grid = (NCH=64, BSZ), 512 threads.
// ===========================================================================
__global__ __launch_bounds__(512)
void stat_pass1_kernel(const float* __restrict__ Are, const float* __restrict__ Aim,
                       const float* __restrict__ gamma, const float* __restrict__ beta)
{
    __shared__ float s_mu[CHUNK], s_rs[CHUNK];
    const int tid  = threadIdx.x;
    const int warp = tid >> 5;
    const int lane = tid & 31;
    const int c = blockIdx.x;
    const int b = blockIdx.y;
    const size_t row0 = (size_t)b * LSEQ + (size_t)c * CHUNK;

#pragma unroll
    for (int j = 0; j < 2; ++j) {
        const int i = warp * 2 + j;
        const float* p = g_h + (row0 + i) * DM;
        float s = 0.0f, s2 = 0.0f;
#pragma unroll
        for (int q = 0; q < 4; ++q) {
            const float4 v = *(const float4*)(p + lane * 4 + q * 128);
            s  += v.x + v.y + v.z + v.w;
            s2 += v.x * v.x + v.y * v.y + v.z * v.z + v.w * v.w;
        }
#pragma unroll
        for (int o = 16; o > 0; o >>= 1) {
            s  += __shfl_xor_sync(0xFFFFFFFFu, s,  o);
            s2 += __shfl_xor_sync(0xFFFFFFFFu, s2, o);
        }
        if (lane == 0) {
            const float mu   = s * (1.0f / DM);
            const float var  = s2 * (1.0f / DM) - mu * mu;
            const float rstd = rsqrtf(var + 1e-5f);
            s_mu[i] = mu;  s_rs[i] = rstd;
            g_mu[row0 + i] = mu;  g_rs[row0 + i] = rstd;
        }
    }
    __syncthreads();

    const int d = tid;
    const float gd = gamma[d], bd = beta[d];
    const float* p = g_h + row0 * DM + d;

    if (c < NSP) {
        const float are = Are[d], aim = Aim[d];
        float s = 0.0f;
        float pre = 1.0f, pim = 0.0f, Sre = 0.0f, Sim = 0.0f;
        for (int i = 0; i < CHUNK; ++i) {
            const float hn = (p[(size_t)i * DM] - s_mu[i]) * s_rs[i] * gd + bd;
            s += hn;
            Sre = fmaf(pre, hn, Sre);
            Sim = fmaf(pim, hn, Sim);
            const float nre = pre * are - pim * aim;
            const float nim = pre * aim + pim * are;
            pre = nre; pim = nim;
        }
        g_csum[(b * NCH + c) * DM + d] = s;
        float wre = 1.0f, wim = 0.0f;
        if (c > 0) {
            float tre = are, tim = aim;
#pragma unroll
            for (int k = 0; k < 5; ++k) {
                const float nr = tre * tre - tim * tim;
                const float ni = 2.0f * tre * tim;
                tre = nr; tim = ni;
            }
            for (int j = 0; j < c; ++j) {
                const float nr = wre * tre - wim * tim;
                const float ni = wre * tim + wim * tre;
                wre = nr; wim = ni;
            }
        }
        g_Sre[(b * NSP + c) * DM + d] = Sre * wre - Sim * wim;
        g_Sim[(b * NSP + c) * DM + d] = Sre * wim + Sim * wre;
    } else {
        float s0 = 0.f, s1 = 0.f;
#pragma unroll 2
        for (int i = 0; i < CHUNK; i += 2) {
            s0 += (p[(size_t)(i + 0) * DM] - s_mu[i + 0]) * s_rs[i + 0];
            s1 += (p[(size_t)(i + 1) * DM] - s_mu[i + 1]) * s_rs[i + 1];
        }
        g_csum[(b * NCH + c) * DM + d] = fmaf(gd, s0 + s1, (float)CHUNK * bd);
    }
}

// ===========================================================================
// Kernel 3: y[l] = hn[l] + ReDc*prefix(hn)[l]; last chunk adds
// Re(BC * A^(L-1-l) * S).  grid = (NCH=64, BSZ), 512 threads.
// ===========================================================================
__global__ __launch_bounds__(512)
void pass2_kernel(float* __restrict__ Y,
                  const float* __restrict__ Are, const float* __restrict__ Aim,
                  const float* __restrict__ Bre, const float* __restrict__ Bim,
                  const float* __restrict__ Cre, const float* __restrict__ Cim,
                  const float* __restrict__ Dre,
                  const float* __restrict__ gamma, const float* __restrict__ beta)
{
    __shared__ float s_mu[CHUNK], s_rs[CHUNK];
    const int d = threadIdx.x;
    const int c = blockIdx.x;
    const int b = blockIdx.y;
    const size_t row0 = (size_t)b * LSEQ + (size_t)c * CHUNK;

    if (d < CHUNK) {
        s_mu[d] = g_mu[row0 + d];
        s_rs[d] = g_rs[row0 + d];
    }
    __syncthreads();

    const float* cs = g_csum + (size_t)b * NCH * DM + d;
    float off = 0.0f;
    for (int cc = 0; cc < c; ++cc) off += cs[(size_t)cc * DM];

    const size_t base = row0 * DM + d;
    const float gd = gamma[d], bd = beta[d];
    const float dre = Dre[d];
    float run = off;
    for (int i = 0; i < CHUNK; ++i) {
        const float hn = (g_h[base + (size_t)i * DM] - s_mu[i]) * s_rs[i] * gd + bd;
        run += hn;
        Y[base + (size_t)i * DM] = fmaf(dre, run, hn);
    }

    if (c == NCH - 1) {
        const float are = Are[d], aim = Aim[d];
        const float bre = Bre[d], bim = Bim[d];
        const float cre = Cre[d], cim = Cim[d];
        const float bcre = bre * cre - bim * cim;
        const float bcim = bre * cim + bim * cre;
        float Sre = 0.0f, Sim = 0.0f;
#pragma unroll
        for (int j = 0; j < NSP; ++j) {
            Sre += g_Sre[(b * NSP + j) * DM + d];
            Sim += g_Sim[(b * NSP + j) * DM + d];
        }
        float qre = 1.0f, qim = 0.0f;
        for (int i = CHUNK - 1; i >= 0; --i) {
            const size_t idx = base + (size_t)i * DM;
            const float zre = qre * Sre - qim * Sim;
            const float zim = qre * Sim + qim * Sre;
            Y[idx] += bcre * zre - bcim * zim;
            const float nre = qre * are - qim * aim;
            const float nim = qre * aim + qim * are;
            qre = nre; qim = nim;
        }
    }
}

// ---------------------------------------------------------------------------
extern "C" void kernel_launch(void* const* d_in, const int* in_sizes, int n_in,
                              void* d_out, int out_size)
{
    const float* x    = (const float*)d_in[0];
    const float* Are  = (const float*)d_in[1];
    const float* Aim  = (const float*)d_in[2];
    const float* Bre  = (const float*)d_in[3];
    const float* Bim  = (const float*)d_in[4];
    const float* Cre  = (const float*)d_in[5];
    const float* Cim  = (const float*)d_in[6];
    const float* Dre  = (const float*)d_in[7];
    const float* W    = (const float*)d_in[9];
    const float* bias = (const float*)d_in[10];
    const float* gamma= (const float*)d_in[11];
    const float* beta = (const float*)d_in[12];
    float* out = (float*)d_out;

    cudaFuncSetAttribute(gemm_mma_kernel,
                         cudaFuncAttributeMaxDynamicSharedMemorySize, SMEM_G);
    cvt_kernel<<<1184, 256>>>(x, W);
    gemm_mma_kernel<<<dim3(DM / 128, MTOT / 128), 256, SMEM_G>>>(bias);
    stat_pass1_kernel<<<dim3(NCH, BSZ), DM>>>(Are, Aim, gamma, beta);
    pass2_kernel<<<dim3(NCH, BSZ), DM>>>(out, Are, Aim, Bre, Bim, Cre, Cim, Dre,
                                         gamma, beta);
}